// round 8
// baseline (speedup 1.0000x reference)
#include <cuda_runtime.h>
#include <cstdint>

// Problem constants
#define BB   8
#define NN   64
#define DD   128
#define HH   4
#define FFD  512
#define ROWS (BB*NN*NN)   // 32768
#define LAYERS 3

// ---------------- scratch (device globals; no runtime allocation) ----------------
// bf16 hi/lo "planes": u32 word = bf16x2 of two consecutive k-elements.
__device__ uint32_t g_tok_hi[(size_t)ROWS*64],  g_tok_lo[(size_t)ROWS*64];   // [M][K/2], K=128
__device__ uint32_t g_qkv_hi[(size_t)ROWS*256], g_qkv_lo[(size_t)ROWS*256];  // [M][512/2]
__device__ uint32_t g_o_hi  [(size_t)ROWS*64],  g_o_lo  [(size_t)ROWS*64];
__device__ uint32_t g_ffn_hi[(size_t)ROWS*256], g_ffn_lo[(size_t)ROWS*256];
__device__ float    g_tmp[(size_t)ROWS*128];                                  // pre-LN fp32
// packed-transposed weights: B_T planes [L][N][K/2]
__device__ uint32_t g_wqkv_hi[3*512*64], g_wqkv_lo[3*512*64];
__device__ uint32_t g_wo_hi [3*128*64],  g_wo_lo [3*128*64];
__device__ uint32_t g_w1_hi [3*512*64],  g_w1_lo [3*512*64];
__device__ uint32_t g_w2_hi [3*128*256], g_w2_lo [3*128*256];
__device__ int g_maskflag;

// ---------------- bf16 split/reconstruct helpers ----------------
__device__ __forceinline__ void split2(float x0, float x1, uint32_t& h, uint32_t& l)
{
    uint32_t hh;
    asm("cvt.rn.bf16x2.f32 %0, %1, %2;" : "=r"(hh) : "f"(x1), "f"(x0));  // hi16=x1, lo16=x0
    float h0 = __uint_as_float(hh << 16);
    float h1 = __uint_as_float(hh & 0xFFFF0000u);
    float l0 = x0 - h0, l1 = x1 - h1;
    uint32_t ll;
    asm("cvt.rn.bf16x2.f32 %0, %1, %2;" : "=r"(ll) : "f"(l1), "f"(l0));
    h = hh; l = ll;
}
__device__ __forceinline__ float2 recon2(uint32_t h, uint32_t l)
{
    return make_float2(__uint_as_float(h << 16)         + __uint_as_float(l << 16),
                       __uint_as_float(h & 0xFFFF0000u) + __uint_as_float(l & 0xFFFF0000u));
}

__device__ __forceinline__ void mma16(float* c, const uint32_t a[4], uint32_t b0, uint32_t b1)
{
    asm volatile(
        "mma.sync.aligned.m16n8k16.row.col.f32.bf16.bf16.f32 "
        "{%0,%1,%2,%3},{%4,%5,%6,%7},{%8,%9},{%0,%1,%2,%3};"
        : "+f"(c[0]), "+f"(c[1]), "+f"(c[2]), "+f"(c[3])
        : "r"(a[0]), "r"(a[1]), "r"(a[2]), "r"(a[3]), "r"(b0), "r"(b1));
}

// ---------------- edge_mask dtype detection ----------------
__global__ void detect_mask_kernel(const unsigned char* __restrict__ p)
{
    __shared__ int sA, sB;
    if (threadIdx.x == 0) { sA = 0; sB = 0; }
    __syncthreads();
    int a = 0, bn = 0;
    for (int i = threadIdx.x; i < 8192; i += blockDim.x) {
        unsigned char b0 = p[4*i+0], b1 = p[4*i+1], b2 = p[4*i+2], b3 = p[4*i+3];
        a  |= b0;
        bn |= (b1 | b2 | b3);
    }
    if (a)  atomicOr(&sA, 1);
    if (bn) atomicOr(&sB, 1);
    __syncthreads();
    if (threadIdx.x == 0) {
        int f;
        if (sA && sB)  f = 0;   // uint8
        else if (!sB)  f = 1;   // int32
        else           f = 2;   // float32
        g_maskflag = f;
    }
}

// ---------------- weight packing (fp32 [L][K][N] -> planes [L][N][K/2]) ----------------
__global__ void pack_qkv_all(const float* __restrict__ Wq, const float* __restrict__ Wk,
                             const float* __restrict__ Wv1, const float* __restrict__ Wv2,
                             uint32_t* __restrict__ hi, uint32_t* __restrict__ lo)
{
    int idx = blockIdx.x * 256 + threadIdx.x;    // 3*512*64 = 98304
    int l = idx >> 15;
    int rem = idx & 32767;
    int n = rem >> 6, kp = rem & 63;
    int seg = n >> 7, nn = n & 127;
    const float* W = (seg == 0) ? Wq : (seg == 1) ? Wk : (seg == 2) ? Wv1 : Wv2;
    W += (size_t)l * 16384;
    float v0 = W[(2*kp) * 128 + nn], v1 = W[(2*kp+1) * 128 + nn];
    uint32_t h, lw; split2(v0, v1, h, lw);
    hi[idx] = h; lo[idx] = lw;
}

__global__ void pack_w(const float* __restrict__ W, uint32_t* __restrict__ hi,
                       uint32_t* __restrict__ lo, int K, int N)
{
    int idx = blockIdx.x * 256 + threadIdx.x;    // L*N*(K/2)
    int Kw = K >> 1;
    int per = N * Kw;
    int l = idx / per, rem = idx - l * per;
    int n = rem / Kw, kp = rem - n * Kw;
    const float* Wl = W + (size_t)l * K * N;
    float v0 = Wl[(2*kp) * N + n], v1 = Wl[(2*kp+1) * N + n];
    uint32_t h, lw; split2(v0, v1, h, lw);
    hi[idx] = h; lo[idx] = lw;
}

// ---------------- token embedding -> tok planes ----------------
__global__ void embed_kernel(const float* __restrict__ x, const float* __restrict__ ea,
                             const void* __restrict__ mask,
                             const float* __restrict__ nW, const float* __restrict__ nb,
                             const float* __restrict__ eW, const float* __restrict__ eb,
                             const float* __restrict__ noe,
                             uint32_t* __restrict__ th, uint32_t* __restrict__ tl)
{
    int t = threadIdx.x; int lr = t >> 6, e = t & 63;
    int bij = blockIdx.x * 4 + lr;
    int j = bij & 63, i = (bij >> 6) & 63, b = bij >> 12;
    float v0, v1;
    if (i == j) {
        float2 nb2 = *(const float2*)&nb[2*e]; v0 = nb2.x; v1 = nb2.y;
        const float* xr = x + (size_t)(b*64 + i) * 16;
        #pragma unroll
        for (int c = 0; c < 16; c++) {
            float2 w = *(const float2*)&nW[c*128 + 2*e];
            v0 = fmaf(xr[c], w.x, v0); v1 = fmaf(xr[c], w.y, v1);
        }
    } else {
        int f = g_maskflag;
        bool m;
        if (f == 0)      m = ((const unsigned char*)mask)[bij] != 0;
        else if (f == 1) m = ((const int*)mask)[bij] != 0;
        else             m = ((const float*)mask)[bij] != 0.0f;
        if (m) {
            float2 eb2 = *(const float2*)&eb[2*e]; v0 = eb2.x; v1 = eb2.y;
            const float* er = ea + (size_t)bij * 8;
            #pragma unroll
            for (int c = 0; c < 8; c++) {
                float2 w = *(const float2*)&eW[c*128 + 2*e];
                v0 = fmaf(er[c], w.x, v0); v1 = fmaf(er[c], w.y, v1);
            }
        } else {
            float2 nn2 = *(const float2*)&noe[2*e]; v0 = nn2.x; v1 = nn2.y;
        }
    }
    uint32_t h, l; split2(v0, v1, h, l);
    th[(size_t)bij * 64 + e] = h;
    tl[(size_t)bij * 64 + e] = l;
}

// ---------------- bf16x3 tensor-core GEMM on pre-split planes ----------------
// C[M,N] = A[M,K] @ B[K,N]; A planes [M][Kw], B_T planes [N][Kw] (Kw=K/2 u32 words).
// block 128x128, BK=32 (16 words), 8 warps 4x2, warp tile 32x64, cp.async 2-stage.
#define PITCH 20                  // u32 words per smem row (conflict-free: 20g+tg distinct mod 32)
#define STGW  (4*128*PITCH)       // 4 arrays per stage = 10240 words
#define GEMM_SMEM (2*STGW*4)      // 81920 bytes

template<bool PLANES, bool BIAS, bool RELU, bool RESID>
__global__ void __launch_bounds__(256, 2) gemm_bf3(
    const uint32_t* __restrict__ Ahi, const uint32_t* __restrict__ Alo,
    const uint32_t* __restrict__ Bhi, const uint32_t* __restrict__ Blo,
    const float* __restrict__ bias,
    const uint32_t* __restrict__ Rhi, const uint32_t* __restrict__ Rlo,
    float* __restrict__ Cf, uint32_t* __restrict__ Chi, uint32_t* __restrict__ Clo,
    int Kw, int N)
{
    extern __shared__ uint32_t smw[];
    uint32_t sbase = (uint32_t)__cvta_generic_to_shared(smw);
    int bm = blockIdx.x, bn = blockIdx.y;
    int t = threadIdx.x, lane = t & 31, w = t >> 5;
    int wm = w & 3, wn = w >> 2, g = lane >> 2, tg = lane & 3;
    int Nw = N >> 1;

    const uint32_t* Ab_hi = Ahi + (size_t)bm * 128 * Kw;
    const uint32_t* Ab_lo = Alo + (size_t)bm * 128 * Kw;
    const uint32_t* Bb_hi = Bhi + (size_t)bn * 128 * Kw;
    const uint32_t* Bb_lo = Blo + (size_t)bn * 128 * Kw;

    auto load = [&](int ch, int st) {
        int kp0 = ch * 16;
        uint32_t base = sbase + (uint32_t)st * STGW * 4u;
        #pragma unroll
        for (int i = 0; i < 2; i++) {
            int idx = t + i * 256;
            int row = idx >> 2, grp = (idx & 3) << 2;
            uint32_t doff = (uint32_t)(row * PITCH + grp) * 4u;
            size_t goff = (size_t)row * Kw + kp0 + grp;
            asm volatile("cp.async.ca.shared.global [%0],[%1],16;" :: "r"(base + doff),            "l"(Ab_hi + goff));
            asm volatile("cp.async.ca.shared.global [%0],[%1],16;" :: "r"(base + 2560*4 + doff),   "l"(Ab_lo + goff));
            asm volatile("cp.async.ca.shared.global [%0],[%1],16;" :: "r"(base + 5120*4 + doff),   "l"(Bb_hi + goff));
            asm volatile("cp.async.ca.shared.global [%0],[%1],16;" :: "r"(base + 7680*4 + doff),   "l"(Bb_lo + goff));
        }
        asm volatile("cp.async.commit_group;");
    };

    float acc[2][8][4] = {};
    int nch = Kw >> 4;
    load(0, 0);
    for (int c = 0; c < nch; c++) {
        int st = c & 1;
        if (c + 1 < nch) {
            load(c + 1, st ^ 1);
            asm volatile("cp.async.wait_group 1;");
        } else {
            asm volatile("cp.async.wait_group 0;");
        }
        __syncthreads();
        const uint32_t* sAhi = smw + st * STGW;
        const uint32_t* sAlo = sAhi + 2560;
        const uint32_t* sBhi = sAhi + 5120;
        const uint32_t* sBlo = sAhi + 7680;

        #pragma unroll
        for (int ks = 0; ks < 2; ks++) {
            int kw = ks * 8 + tg;
            uint32_t ah[2][4], al[2][4];
            #pragma unroll
            for (int mt = 0; mt < 2; mt++) {
                int r = wm * 32 + mt * 16 + g;
                ah[mt][0] = sAhi[r*PITCH + kw];       ah[mt][1] = sAhi[(r+8)*PITCH + kw];
                ah[mt][2] = sAhi[r*PITCH + kw + 4];   ah[mt][3] = sAhi[(r+8)*PITCH + kw + 4];
                al[mt][0] = sAlo[r*PITCH + kw];       al[mt][1] = sAlo[(r+8)*PITCH + kw];
                al[mt][2] = sAlo[r*PITCH + kw + 4];   al[mt][3] = sAlo[(r+8)*PITCH + kw + 4];
            }
            #pragma unroll
            for (int nt = 0; nt < 8; nt++) {
                int n = wn * 64 + nt * 8 + g;
                uint32_t bh0 = sBhi[n*PITCH + kw], bh1 = sBhi[n*PITCH + kw + 4];
                uint32_t bl0 = sBlo[n*PITCH + kw], bl1 = sBlo[n*PITCH + kw + 4];
                #pragma unroll
                for (int mt = 0; mt < 2; mt++) {
                    mma16(acc[mt][nt], ah[mt], bh0, bh1);   // ahi*bhi
                    mma16(acc[mt][nt], ah[mt], bl0, bl1);   // ahi*blo
                    mma16(acc[mt][nt], al[mt], bh0, bh1);   // alo*bhi
                }
            }
        }
        __syncthreads();
    }

    // epilogue: (c0,c1) at (row, 2cw..2cw+1); (c2,c3) at row+8
    #pragma unroll
    for (int mt = 0; mt < 2; mt++) {
        #pragma unroll
        for (int nt = 0; nt < 8; nt++) {
            int cw = bn * 64 + wn * 32 + nt * 4 + tg;
            float bs0 = 0.f, bs1 = 0.f;
            if (BIAS) { float2 bb = *(const float2*)&bias[cw * 2]; bs0 = bb.x; bs1 = bb.y; }
            #pragma unroll
            for (int rr = 0; rr < 2; rr++) {
                int r = bm * 128 + wm * 32 + mt * 16 + g + rr * 8;
                float v0 = acc[mt][nt][rr*2 + 0] + bs0;
                float v1 = acc[mt][nt][rr*2 + 1] + bs1;
                if (RELU) { v0 = fmaxf(v0, 0.f); v1 = fmaxf(v1, 0.f); }
                if (RESID) {   // resid = tok planes (N=128 -> pitch 64)
                    float2 rv = recon2(Rhi[(size_t)r * 64 + cw], Rlo[(size_t)r * 64 + cw]);
                    v0 += rv.x; v1 += rv.y;
                }
                if (PLANES) {
                    uint32_t h, l; split2(v0, v1, h, l);
                    Chi[(size_t)r * Nw + cw] = h;
                    Clo[(size_t)r * Nw + cw] = l;
                } else {
                    *(float2*)&Cf[(size_t)r * N + cw * 2] = make_float2(v0, v1);
                }
            }
        }
    }
}

// ---------------- triangular attention (planes in, planes out, 4-i tile) ----------------
// qkv word layout per row (256 words): q 0..63 | k 64..127 | v1 128..191 | v2 192..255
#define ATTN_SMEM 131072
__global__ void __launch_bounds__(256) attn_kernel(
    const uint32_t* __restrict__ qhi, const uint32_t* __restrict__ qlo,
    uint32_t* __restrict__ ohi, uint32_t* __restrict__ olo)
{
    extern __shared__ float sm[];
    float* q_s  = sm;            // [4][64][32]
    float* v1_s = sm + 8192;     // [4][64][32]
    float* s_s  = sm + 16384;    // [4][64][64]

    int bx = blockIdx.x;                 // 8*4*16 = 512
    int ig = bx & 15, h = (bx >> 4) & 3, b = bx >> 6;
    int i0 = ig * 4;
    int t = threadIdx.x;

    // stage q, v1 (reconstructed fp32)
    for (int idx = t; idx < 4096; idx += 256) {
        int wd = idx & 15, l = (idx >> 4) & 63, ii = idx >> 10;
        size_t off = (size_t)((b*64 + i0 + ii) * 64 + l) * 256 + h * 16 + wd;
        float2 f = recon2(qhi[off], qlo[off]);
        q_s[ii*2048 + l*32 + wd*2]     = f.x;
        q_s[ii*2048 + l*32 + wd*2 + 1] = f.y;
        float2 f2 = recon2(qhi[off + 128], qlo[off + 128]);
        v1_s[ii*2048 + l*32 + wd*2]     = f2.x;
        v1_s[ii*2048 + l*32 + wd*2 + 1] = f2.y;
    }
    __syncthreads();

    int j = t >> 2, c = t & 3;
    size_t bj = (size_t)(b * 4096 + j) * 256 + h * 16 + c * 4;

    // ---- pass 1: scores ----
    for (int l = 0; l < 64; l++) {
        size_t off = bj + (size_t)l * 64 * 256 + 64;    // k
        uint4 kh = *(const uint4*)(qhi + off);
        uint4 kl = *(const uint4*)(qlo + off);
        float kf[8];
        { float2 f;
          f = recon2(kh.x, kl.x); kf[0]=f.x; kf[1]=f.y;
          f = recon2(kh.y, kl.y); kf[2]=f.x; kf[3]=f.y;
          f = recon2(kh.z, kl.z); kf[4]=f.x; kf[5]=f.y;
          f = recon2(kh.w, kl.w); kf[6]=f.x; kf[7]=f.y; }
        float p[4];
        #pragma unroll
        for (int ii = 0; ii < 4; ii++) {
            const float* qp = q_s + ii*2048 + l*32 + c*8;
            float4 a = *(const float4*)qp, bq = *(const float4*)(qp + 4);
            p[ii] = a.x*kf[0] + a.y*kf[1] + a.z*kf[2] + a.w*kf[3]
                  + bq.x*kf[4] + bq.y*kf[5] + bq.z*kf[6] + bq.w*kf[7];
            p[ii] += __shfl_xor_sync(0xffffffffu, p[ii], 1);
            p[ii] += __shfl_xor_sync(0xffffffffu, p[ii], 2);
        }
        if (c == 0) {
            #pragma unroll
            for (int ii = 0; ii < 4; ii++) s_s[ii*4096 + l*64 + j] = p[ii];
        }
    }
    __syncthreads();

    // ---- softmax over l (all 256 threads: 4 ii x 64 jj) ----
    {
        int ii = t >> 6, jj = t & 63;
        float* col = s_s + ii * 4096 + jj;
        const float invs = 0.17677669529663687f;    // 1/sqrt(32)
        float m = -1e30f;
        for (int l = 0; l < 64; l++) { float v = col[l*64] * invs; col[l*64] = v; m = fmaxf(m, v); }
        float z = 0.f;
        for (int l = 0; l < 64; l++) { float e = __expf(col[l*64] - m); col[l*64] = e; z += e; }
        float iz = 1.f / z;
        for (int l = 0; l < 64; l++) col[l*64] *= iz;
    }
    __syncthreads();

    // ---- pass 2: output ----
    float o[4][8] = {};
    for (int l = 0; l < 64; l++) {
        size_t off = bj + (size_t)l * 64 * 256 + 192;   // v2
        uint4 vh = *(const uint4*)(qhi + off);
        uint4 vl = *(const uint4*)(qlo + off);
        float vf[8];
        { float2 f;
          f = recon2(vh.x, vl.x); vf[0]=f.x; vf[1]=f.y;
          f = recon2(vh.y, vl.y); vf[2]=f.x; vf[3]=f.y;
          f = recon2(vh.z, vl.z); vf[4]=f.x; vf[5]=f.y;
          f = recon2(vh.w, vl.w); vf[6]=f.x; vf[7]=f.y; }
        #pragma unroll
        for (int ii = 0; ii < 4; ii++) {
            float a = s_s[ii*4096 + l*64 + j];
            const float* up = v1_s + ii*2048 + l*32 + c*8;
            float4 u0 = *(const float4*)up, u1 = *(const float4*)(up + 4);
            float uu[8] = {u0.x, u0.y, u0.z, u0.w, u1.x, u1.y, u1.z, u1.w};
            #pragma unroll
            for (int dd = 0; dd < 8; dd++)
                o[ii][dd] = fmaf(a * uu[dd], vf[dd], o[ii][dd]);
        }
    }
    #pragma unroll
    for (int ii = 0; ii < 4; ii++) {
        size_t off = (size_t)((b*64 + i0 + ii) * 64 + j) * 64 + h * 16 + c * 4;
        uint32_t h0,l0,h1,l1,h2,l2,h3,l3;
        split2(o[ii][0], o[ii][1], h0, l0);
        split2(o[ii][2], o[ii][3], h1, l1);
        split2(o[ii][4], o[ii][5], h2, l2);
        split2(o[ii][6], o[ii][7], h3, l3);
        *(uint4*)(ohi + off) = make_uint4(h0, h1, h2, h3);
        *(uint4*)(olo + off) = make_uint4(l0, l1, l2, l3);
    }
}

// ---------------- LayerNorm fp32 -> tok planes (4 rows/block) ----------------
__global__ void ln_kernel(const float* __restrict__ in, const float* __restrict__ gg,
                          const float* __restrict__ bb,
                          uint32_t* __restrict__ th, uint32_t* __restrict__ tl)
{
    int t = threadIdx.x; int lr = t >> 6, e = t & 63;
    size_t row = (size_t)blockIdx.x * 4 + lr;
    float2 v = *(const float2*)&in[row * 128 + e * 2];
    float s = v.x + v.y, s2 = v.x*v.x + v.y*v.y;
    #pragma unroll
    for (int off = 16; off; off >>= 1) {
        s  += __shfl_xor_sync(0xffffffffu, s,  off);
        s2 += __shfl_xor_sync(0xffffffffu, s2, off);
    }
    __shared__ float ws[8], ws2[8];
    int wid = t >> 5;
    if ((t & 31) == 0) { ws[wid] = s; ws2[wid] = s2; }
    __syncthreads();
    s  = ws[lr*2]  + ws[lr*2 + 1];
    s2 = ws2[lr*2] + ws2[lr*2 + 1];
    float mean = s * (1.f/128.f);
    float var  = s2 * (1.f/128.f) - mean * mean;
    float rs   = rsqrtf(var + 1e-5f);
    float2 gv = *(const float2*)&gg[e*2];
    float2 bv = *(const float2*)&bb[e*2];
    float o0 = (v.x - mean) * rs * gv.x + bv.x;
    float o1 = (v.y - mean) * rs * gv.y + bv.y;
    uint32_t h, l; split2(o0, o1, h, l);
    th[row * 64 + e] = h;
    tl[row * 64 + e] = l;
}

// ---------------- final diagonal readout ----------------
__global__ void out_kernel(const float* __restrict__ Wout, const float* __restrict__ bout,
                           float* __restrict__ out)
{
    int rowid = blockIdx.x;       // 512
    int b = rowid >> 6, n = rowid & 63;
    int t = threadIdx.x;          // 64
    size_t row = (size_t)((b*64 + n) * 64 + n);
    float2 f = recon2(g_tok_hi[row * 64 + t], g_tok_lo[row * 64 + t]);
    float v = f.x * Wout[2*t] + f.y * Wout[2*t + 1];
    #pragma unroll
    for (int off = 16; off; off >>= 1) v += __shfl_xor_sync(0xffffffffu, v, off);
    __shared__ float ws[2];
    if ((t & 31) == 0) ws[t >> 5] = v;
    __syncthreads();
    if (t == 0) out[rowid] = ws[0] + ws[1] + bout[0];
}

// ---------------- host launcher ----------------
extern "C" void kernel_launch(void* const* d_in, const int* in_sizes, int n_in,
                              void* d_out, int out_size)
{
    const float* x         = (const float*)d_in[0];
    const float* edge_attr = (const float*)d_in[1];
    const void*  edge_mask = (const void*) d_in[2];
    const float* node_W    = (const float*)d_in[3];
    const float* node_b    = (const float*)d_in[4];
    const float* edge_W    = (const float*)d_in[5];
    const float* edge_b    = (const float*)d_in[6];
    const float* no_edge   = (const float*)d_in[7];
    const float* Wq        = (const float*)d_in[8];
    const float* Wk        = (const float*)d_in[9];
    const float* Wv1       = (const float*)d_in[10];
    const float* Wv2       = (const float*)d_in[11];
    const float* Wo        = (const float*)d_in[12];
    const float* bo        = (const float*)d_in[13];
    const float* ln1_g     = (const float*)d_in[14];
    const float* ln1_b     = (const float*)d_in[15];
    const float* W1        = (const float*)d_in[16];
    const float* b1        = (const float*)d_in[17];
    const float* W2        = (const float*)d_in[18];
    const float* b2        = (const float*)d_in[19];
    const float* ln2_g     = (const float*)d_in[20];
    const float* ln2_b     = (const float*)d_in[21];
    const float* Wout      = (const float*)d_in[22];
    const float* bout      = (const float*)d_in[23];

    uint32_t *tok_hi, *tok_lo, *qkv_hi, *qkv_lo, *o_hi, *o_lo, *ffn_hi, *ffn_lo;
    uint32_t *wqkv_hi, *wqkv_lo, *wo_hi, *wo_lo, *w1_hi, *w1_lo, *w2_hi, *w2_lo;
    float* tmpp;
    cudaGetSymbolAddress((void**)&tok_hi, g_tok_hi);   cudaGetSymbolAddress((void**)&tok_lo, g_tok_lo);
    cudaGetSymbolAddress((void**)&qkv_hi, g_qkv_hi);   cudaGetSymbolAddress((void**)&qkv_lo, g_qkv_lo);
    cudaGetSymbolAddress((void**)&o_hi,   g_o_hi);     cudaGetSymbolAddress((void**)&o_lo,   g_o_lo);
    cudaGetSymbolAddress((void**)&ffn_hi, g_ffn_hi);   cudaGetSymbolAddress((void**)&ffn_lo, g_ffn_lo);
    cudaGetSymbolAddress((void**)&wqkv_hi, g_wqkv_hi); cudaGetSymbolAddress((void**)&wqkv_lo, g_wqkv_lo);
    cudaGetSymbolAddress((void**)&wo_hi,  g_wo_hi);    cudaGetSymbolAddress((void**)&wo_lo,  g_wo_lo);
    cudaGetSymbolAddress((void**)&w1_hi,  g_w1_hi);    cudaGetSymbolAddress((void**)&w1_lo,  g_w1_lo);
    cudaGetSymbolAddress((void**)&w2_hi,  g_w2_hi);    cudaGetSymbolAddress((void**)&w2_lo,  g_w2_lo);
    cudaGetSymbolAddress((void**)&tmpp,   g_tmp);

    cudaFuncSetAttribute(attn_kernel, cudaFuncAttributeMaxDynamicSharedMemorySize, ATTN_SMEM);
    cudaFuncSetAttribute(gemm_bf3<true,false,false,false>, cudaFuncAttributeMaxDynamicSharedMemorySize, GEMM_SMEM);
    cudaFuncSetAttribute(gemm_bf3<false,true,false,true>,  cudaFuncAttributeMaxDynamicSharedMemorySize, GEMM_SMEM);
    cudaFuncSetAttribute(gemm_bf3<true,true,true,false>,   cudaFuncAttributeMaxDynamicSharedMemorySize, GEMM_SMEM);

    detect_mask_kernel<<<1, 256>>>((const unsigned char*)edge_mask);
    pack_qkv_all<<<384, 256>>>(Wq, Wk, Wv1, Wv2, wqkv_hi, wqkv_lo);
    pack_w<<<96, 256>>> (Wo, wo_hi, wo_lo, 128, 128);   // 3*128*64
    pack_w<<<384, 256>>>(W1, w1_hi, w1_lo, 128, 512);   // 3*512*64
    pack_w<<<384, 256>>>(W2, w2_hi, w2_lo, 512, 128);   // 3*128*256
    embed_kernel<<<ROWS/4, 256>>>(x, edge_attr, edge_mask, node_W, node_b,
                                  edge_W, edge_b, no_edge, tok_hi, tok_lo);

    const dim3 gN128(ROWS/128, 1);
    const dim3 gN512(ROWS/128, 4);

    for (int l = 0; l < LAYERS; l++) {
        // fused QKV projection -> qkv planes
        gemm_bf3<true,false,false,false><<<gN512, 256, GEMM_SMEM>>>(
            tok_hi, tok_lo, wqkv_hi + l*32768, wqkv_lo + l*32768,
            nullptr, nullptr, nullptr, nullptr, qkv_hi, qkv_lo, 64, 512);

        attn_kernel<<<512, 256, ATTN_SMEM>>>(qkv_hi, qkv_lo, o_hi, o_lo);

        // pre-LN1 = tok + o@Wo + bo -> tmp (fp32)
        gemm_bf3<false,true,false,true><<<gN128, 256, GEMM_SMEM>>>(
            o_hi, o_lo, wo_hi + l*8192, wo_lo + l*8192,
            bo + l*128, tok_hi, tok_lo, tmpp, nullptr, nullptr, 64, 128);
        ln_kernel<<<ROWS/4, 256>>>(tmpp, ln1_g + l*128, ln1_b + l*128, tok_hi, tok_lo);

        // FFN up (relu) -> ffn planes
        gemm_bf3<true,true,true,false><<<gN512, 256, GEMM_SMEM>>>(
            tok_hi, tok_lo, w1_hi + l*32768, w1_lo + l*32768,
            b1 + l*512, nullptr, nullptr, nullptr, ffn_hi, ffn_lo, 64, 512);

        // FFN down + resid -> tmp (fp32)
        gemm_bf3<false,true,false,true><<<gN128, 256, GEMM_SMEM>>>(
            ffn_hi, ffn_lo, w2_hi + l*32768, w2_lo + l*32768,
            b2 + l*128, tok_hi, tok_lo, tmpp, nullptr, nullptr, 256, 128);
        ln_kernel<<<ROWS/4, 256>>>(tmpp, ln2_g + l*128, ln2_b + l*128, tok_hi, tok_lo);
    }

    out_kernel<<<BB*NN, 64>>>(Wout, bout, (float*)d_out);
}